// round 1
// baseline (speedup 1.0000x reference)
#include <cuda_runtime.h>

#define ADIM 64
#define NDIM 128
#define HDIM 8

__device__ __forceinline__ unsigned long long pack2(float lo, float hi) {
    unsigned long long r;
    asm("mov.b64 %0, {%1,%2};" : "=l"(r) : "f"(lo), "f"(hi));
    return r;
}
__device__ __forceinline__ void unpack2(unsigned long long v, float &lo, float &hi) {
    asm("mov.b64 {%0,%1}, %2;" : "=f"(lo), "=f"(hi) : "l"(v));
}
__device__ __forceinline__ void fma2(unsigned long long &d, unsigned long long a, unsigned long long b) {
    asm("fma.rn.f32x2 %0, %1, %2, %0;" : "+l"(d) : "l"(a), "l"(b));
}

__global__ void __launch_bounds__(256) attn_kernel(
    const float* __restrict__ S,
    const float* __restrict__ Wq,
    const float* __restrict__ bq,
    const float* __restrict__ Wk,
    const float* __restrict__ bk,
    float* __restrict__ out)
{
    __shared__ __align__(16) float sW[NDIM * 16];   // [n][0..7]=Wq row, [8..15]=Wk row
    __shared__ __align__(16) float sBias[16];
    __shared__ __align__(16) float sQ[ADIM * HDIM]; // qflat[a*8+h]
    __shared__ __align__(16) float sK[ADIM * HDIM]; // kflat[a*8+h]; kres[h][j]=sK[h*64+j]
    __shared__ __align__(16) float sRed[4096];      // reduction scratch, then output staging

    const int t  = threadIdx.x;
    const int tb = blockIdx.x;

    // ---- load weights + biases into smem (coalesced-ish, tiny) ----
    for (int idx = t; idx < NDIM * 16; idx += 256) {
        int n = idx >> 4, h = idx & 15;
        sW[idx] = (h < 8) ? Wq[n * 8 + h] : Wk[n * 8 + (h - 8)];
    }
    if (t < 16) sBias[t] = (t < 8) ? bq[t] : bk[t - 8];

    // ---- phase 1: S quarter-row straight to registers ----
    // thread (a, qu): a = t&63 row, qu = t>>6 quarter of the 128-wide row.
    // Each warp has a fixed qu; its 8 LDG.128 cover 32 full 128B lines.
    const int a  = t & 63;
    const int qu = t >> 6;
    float sloc[32];
    {
        const float4* srow = reinterpret_cast<const float4*>(
            S + (size_t)tb * (ADIM * NDIM) + a * NDIM + qu * 32);
        #pragma unroll
        for (int i = 0; i < 8; i++) {
            float4 v = srow[i];
            sloc[4*i+0] = v.x; sloc[4*i+1] = v.y; sloc[4*i+2] = v.z; sloc[4*i+3] = v.w;
        }
    }
    __syncthreads();  // sW / sBias ready

    // ---- phase 2: partial Q,K projections with packed FFMA2 ----
    // acc[0..3] = q[a][h-pairs], acc[4..7] = k[a][h-pairs] (partial over this quarter's n)
    unsigned long long acc[8];
    #pragma unroll
    for (int p = 0; p < 8; p++) acc[p] = 0ull;
    #pragma unroll
    for (int nn = 0; nn < 32; nn++) {
        float s = sloc[nn];
        unsigned long long ss = pack2(s, s);
        const ulonglong2* wrow = reinterpret_cast<const ulonglong2*>(sW + (qu * 32 + nn) * 16);
        ulonglong2 w0 = wrow[0], w1 = wrow[1], w2 = wrow[2], w3 = wrow[3];
        fma2(acc[0], ss, w0.x); fma2(acc[1], ss, w0.y);
        fma2(acc[2], ss, w1.x); fma2(acc[3], ss, w1.y);
        fma2(acc[4], ss, w2.x); fma2(acc[5], ss, w2.y);
        fma2(acc[6], ss, w3.x); fma2(acc[7], ss, w3.y);
    }
    // write partials (bank-rotated by a to avoid 16-way STS conflicts)
    {
        float4* red4 = reinterpret_cast<float4*>(sRed);
        #pragma unroll
        for (int c = 0; c < 4; c++) {
            float x0, x1, y0, y1;
            unpack2(acc[2*c],     x0, x1);
            unpack2(acc[2*c + 1], y0, y1);
            red4[(qu * 64 + a) * 4 + ((c + a) & 3)] = make_float4(x0, x1, y0, y1);
        }
    }
    __syncthreads();
    // reduce the 4 quarter-partials, add bias, scatter to sQ / sK (kflat row-major)
    {
        const int a2 = t >> 2, c = t & 3;  // c: 0,1 -> q chunks; 2,3 -> k chunks
        const float4* red4 = reinterpret_cast<const float4*>(sRed);
        float4 v = make_float4(0.f, 0.f, 0.f, 0.f);
        #pragma unroll
        for (int qq = 0; qq < 4; qq++) {
            float4 p = red4[(qq * 64 + a2) * 4 + ((c + a2) & 3)];
            v.x += p.x; v.y += p.y; v.z += p.z; v.w += p.w;
        }
        v.x += sBias[c*4+0]; v.y += sBias[c*4+1]; v.z += sBias[c*4+2]; v.w += sBias[c*4+3];
        if (c < 2) reinterpret_cast<float4*>(sQ)[a2 * 2 + c]       = v;
        else       reinterpret_cast<float4*>(sK)[a2 * 2 + (c - 2)] = v;
    }
    __syncthreads();

    // ---- phase 3: att row = q[i] . kres[:, j], 4 threads per row, 16 j each ----
    const int i  = t >> 2;
    const int jg = t & 3;
    unsigned long long accA[8];
    #pragma unroll
    for (int p = 0; p < 8; p++) accA[p] = 0ull;
    const float* qrow = sQ + i * HDIM;
    #pragma unroll
    for (int h = 0; h < HDIM; h++) {
        float qv = qrow[h];
        unsigned long long qq = pack2(qv, qv);
        // reshape semantics: kres[h][j] = kflat[h*64 + j]
        const ulonglong2* kp = reinterpret_cast<const ulonglong2*>(sK + h * 64 + jg * 16);
        ulonglong2 k0 = kp[0], k1 = kp[1], k2 = kp[2], k3 = kp[3];
        fma2(accA[0], qq, k0.x); fma2(accA[1], qq, k0.y);
        fma2(accA[2], qq, k1.x); fma2(accA[3], qq, k1.y);
        fma2(accA[4], qq, k2.x); fma2(accA[5], qq, k2.y);
        fma2(accA[6], qq, k3.x); fma2(accA[7], qq, k3.y);
    }
    float v[16];
    #pragma unroll
    for (int p = 0; p < 8; p++) unpack2(accA[p], v[2*p], v[2*p + 1]);

    // ---- softmax across the 4-lane row group ----
    float m = v[0];
    #pragma unroll
    for (int p = 1; p < 16; p++) m = fmaxf(m, v[p]);
    m = fmaxf(m, __shfl_xor_sync(0xffffffffu, m, 1));
    m = fmaxf(m, __shfl_xor_sync(0xffffffffu, m, 2));
    float ssum = 0.f;
    #pragma unroll
    for (int p = 0; p < 16; p++) { v[p] = __expf(v[p] - m); ssum += v[p]; }
    ssum += __shfl_xor_sync(0xffffffffu, ssum, 1);
    ssum += __shfl_xor_sync(0xffffffffu, ssum, 2);
    const float inv = __fdividef(1.0f, ssum);

    // ---- diagonal removal: stage compacted 63-wide rows in sRed ----
    __syncthreads();  // everyone done reading sRed partials (already true, but cheap & safe)
    {
        float* orow = sRed + i * 63;
        const int jbase = jg * 16;
        #pragma unroll
        for (int p = 0; p < 16; p++) {
            int j = jbase + p;
            if (j != i) orow[j - (j > i)] = v[p] * inv;
        }
    }
    __syncthreads();

    // ---- cooperative 16B-aligned store: 4032 contiguous floats per CTA ----
    float4* dst = reinterpret_cast<float4*>(out) + (size_t)tb * 1008;
    const float4* src = reinterpret_cast<const float4*>(sRed);
    #pragma unroll
    for (int r = 0; r < 4; r++) {
        int idx = t + r * 256;
        if (idx < 1008) dst[idx] = src[idx];
    }
}

extern "C" void kernel_launch(void* const* d_in, const int* in_sizes, int n_in,
                              void* d_out, int out_size)
{
    const float* S  = (const float*)d_in[0];
    const float* Wq = (const float*)d_in[1];
    const float* bq = (const float*)d_in[2];
    const float* Wk = (const float*)d_in[3];
    const float* bk = (const float*)d_in[4];
    int tb_total = in_sizes[0] / (ADIM * NDIM);   // 512*32 = 16384 tiles
    attn_kernel<<<tb_total, 256>>>(S, Wq, bq, Wk, bk, (float*)d_out);
}

// round 2
// speedup vs baseline: 1.0001x; 1.0001x over previous
#include <cuda_runtime.h>

#define ADIM 64
#define NDIM 128
#define HDIM 8

__device__ __forceinline__ unsigned long long pack2(float lo, float hi) {
    unsigned long long r;
    asm("mov.b64 %0, {%1,%2};" : "=l"(r) : "f"(lo), "f"(hi));
    return r;
}
__device__ __forceinline__ void unpack2(unsigned long long v, float &lo, float &hi) {
    asm("mov.b64 {%0,%1}, %2;" : "=f"(lo), "=f"(hi) : "l"(v));
}
__device__ __forceinline__ void fma2(unsigned long long &d, unsigned long long a, unsigned long long b) {
    asm("fma.rn.f32x2 %0, %1, %2, %0;" : "+l"(d) : "l"(a), "l"(b));
}

__global__ void __launch_bounds__(256) attn_kernel(
    const float* __restrict__ S,
    const float* __restrict__ Wq,
    const float* __restrict__ bq,
    const float* __restrict__ Wk,
    const float* __restrict__ bk,
    float* __restrict__ out)
{
    __shared__ __align__(16) float sW[NDIM * 16];   // [n][0..7]=Wq row, [8..15]=Wk row
    __shared__ __align__(16) float sBias[16];
    __shared__ __align__(16) float sQ[ADIM * HDIM]; // qflat[a*8+h]
    __shared__ __align__(16) float sK[ADIM * HDIM]; // kflat[a*8+h]; kres[h][j]=sK[h*64+j]
    __shared__ __align__(16) float sRed[4096];      // reduction scratch, then output staging

    const int t  = threadIdx.x;
    const int tb = blockIdx.x;

    // ---- load weights + biases into smem (coalesced-ish, tiny) ----
    for (int idx = t; idx < NDIM * 16; idx += 256) {
        int n = idx >> 4, h = idx & 15;
        sW[idx] = (h < 8) ? Wq[n * 8 + h] : Wk[n * 8 + (h - 8)];
    }
    if (t < 16) sBias[t] = (t < 8) ? bq[t] : bk[t - 8];

    // ---- phase 1: S quarter-row straight to registers ----
    // thread (a, qu): a = t&63 row, qu = t>>6 quarter of the 128-wide row.
    // Each warp has a fixed qu; its 8 LDG.128 cover 32 full 128B lines.
    const int a  = t & 63;
    const int qu = t >> 6;
    float sloc[32];
    {
        const float4* srow = reinterpret_cast<const float4*>(
            S + (size_t)tb * (ADIM * NDIM) + a * NDIM + qu * 32);
        #pragma unroll
        for (int i = 0; i < 8; i++) {
            float4 v = srow[i];
            sloc[4*i+0] = v.x; sloc[4*i+1] = v.y; sloc[4*i+2] = v.z; sloc[4*i+3] = v.w;
        }
    }
    __syncthreads();  // sW / sBias ready

    // ---- phase 2: partial Q,K projections with packed FFMA2 ----
    // acc[0..3] = q[a][h-pairs], acc[4..7] = k[a][h-pairs] (partial over this quarter's n)
    unsigned long long acc[8];
    #pragma unroll
    for (int p = 0; p < 8; p++) acc[p] = 0ull;
    #pragma unroll
    for (int nn = 0; nn < 32; nn++) {
        float s = sloc[nn];
        unsigned long long ss = pack2(s, s);
        const ulonglong2* wrow = reinterpret_cast<const ulonglong2*>(sW + (qu * 32 + nn) * 16);
        ulonglong2 w0 = wrow[0], w1 = wrow[1], w2 = wrow[2], w3 = wrow[3];
        fma2(acc[0], ss, w0.x); fma2(acc[1], ss, w0.y);
        fma2(acc[2], ss, w1.x); fma2(acc[3], ss, w1.y);
        fma2(acc[4], ss, w2.x); fma2(acc[5], ss, w2.y);
        fma2(acc[6], ss, w3.x); fma2(acc[7], ss, w3.y);
    }
    // write partials (bank-rotated by a to avoid 16-way STS conflicts)
    {
        float4* red4 = reinterpret_cast<float4*>(sRed);
        #pragma unroll
        for (int c = 0; c < 4; c++) {
            float x0, x1, y0, y1;
            unpack2(acc[2*c],     x0, x1);
            unpack2(acc[2*c + 1], y0, y1);
            red4[(qu * 64 + a) * 4 + ((c + a) & 3)] = make_float4(x0, x1, y0, y1);
        }
    }
    __syncthreads();
    // reduce the 4 quarter-partials, add bias, scatter to sQ / sK (kflat row-major)
    {
        const int a2 = t >> 2, c = t & 3;  // c: 0,1 -> q chunks; 2,3 -> k chunks
        const float4* red4 = reinterpret_cast<const float4*>(sRed);
        float4 v = make_float4(0.f, 0.f, 0.f, 0.f);
        #pragma unroll
        for (int qq = 0; qq < 4; qq++) {
            float4 p = red4[(qq * 64 + a2) * 4 + ((c + a2) & 3)];
            v.x += p.x; v.y += p.y; v.z += p.z; v.w += p.w;
        }
        v.x += sBias[c*4+0]; v.y += sBias[c*4+1]; v.z += sBias[c*4+2]; v.w += sBias[c*4+3];
        if (c < 2) reinterpret_cast<float4*>(sQ)[a2 * 2 + c]       = v;
        else       reinterpret_cast<float4*>(sK)[a2 * 2 + (c - 2)] = v;
    }
    __syncthreads();

    // ---- phase 3: att row = q[i] . kres[:, j], 4 threads per row, 16 j each ----
    const int i  = t >> 2;
    const int jg = t & 3;
    unsigned long long accA[8];
    #pragma unroll
    for (int p = 0; p < 8; p++) accA[p] = 0ull;
    const float* qrow = sQ + i * HDIM;
    #pragma unroll
    for (int h = 0; h < HDIM; h++) {
        float qv = qrow[h];
        unsigned long long qq = pack2(qv, qv);
        // reshape semantics: kres[h][j] = kflat[h*64 + j]
        const ulonglong2* kp = reinterpret_cast<const ulonglong2*>(sK + h * 64 + jg * 16);
        ulonglong2 k0 = kp[0], k1 = kp[1], k2 = kp[2], k3 = kp[3];
        fma2(accA[0], qq, k0.x); fma2(accA[1], qq, k0.y);
        fma2(accA[2], qq, k1.x); fma2(accA[3], qq, k1.y);
        fma2(accA[4], qq, k2.x); fma2(accA[5], qq, k2.y);
        fma2(accA[6], qq, k3.x); fma2(accA[7], qq, k3.y);
    }
    float v[16];
    #pragma unroll
    for (int p = 0; p < 8; p++) unpack2(accA[p], v[2*p], v[2*p + 1]);

    // ---- softmax across the 4-lane row group ----
    float m = v[0];
    #pragma unroll
    for (int p = 1; p < 16; p++) m = fmaxf(m, v[p]);
    m = fmaxf(m, __shfl_xor_sync(0xffffffffu, m, 1));
    m = fmaxf(m, __shfl_xor_sync(0xffffffffu, m, 2));
    float ssum = 0.f;
    #pragma unroll
    for (int p = 0; p < 16; p++) { v[p] = __expf(v[p] - m); ssum += v[p]; }
    ssum += __shfl_xor_sync(0xffffffffu, ssum, 1);
    ssum += __shfl_xor_sync(0xffffffffu, ssum, 2);
    const float inv = __fdividef(1.0f, ssum);

    // ---- diagonal removal: stage compacted 63-wide rows in sRed ----
    __syncthreads();  // everyone done reading sRed partials (already true, but cheap & safe)
    {
        float* orow = sRed + i * 63;
        const int jbase = jg * 16;
        #pragma unroll
        for (int p = 0; p < 16; p++) {
            int j = jbase + p;
            if (j != i) orow[j - (j > i)] = v[p] * inv;
        }
    }
    __syncthreads();

    // ---- cooperative 16B-aligned store: 4032 contiguous floats per CTA ----
    float4* dst = reinterpret_cast<float4*>(out) + (size_t)tb * 1008;
    const float4* src = reinterpret_cast<const float4*>(sRed);
    #pragma unroll
    for (int r = 0; r < 4; r++) {
        int idx = t + r * 256;
        if (idx < 1008) dst[idx] = src[idx];
    }
}

extern "C" void kernel_launch(void* const* d_in, const int* in_sizes, int n_in,
                              void* d_out, int out_size)
{
    const float* S  = (const float*)d_in[0];
    const float* Wq = (const float*)d_in[1];
    const float* bq = (const float*)d_in[2];
    const float* Wk = (const float*)d_in[3];
    const float* bk = (const float*)d_in[4];
    int tb_total = in_sizes[0] / (ADIM * NDIM);   // 512*32 = 16384 tiles
    attn_kernel<<<tb_total, 256>>>(S, Wq, bq, Wk, bk, (float*)d_out);
}